// round 1
// baseline (speedup 1.0000x reference)
#include <cuda_runtime.h>
#include <math.h>
#include <stdint.h>

#define SEQ   2048
#define HID   2048
#define INSZ  1024
#define NL    4

// ---------------- persistent device scratch ----------------
__device__ float    g_h[NL][2][HID];       // double-buffered hidden states
__device__ float    g_xin[(size_t)SEQ * HID];   // x @ W_x^T
__device__ float    g_h3[(size_t)SEQ * HID];    // h3(t) for all t (feeds y GEMM)
__device__ unsigned g_cnt = 0;
__device__ unsigned g_gen = 0;

// ---------------- grid-wide barrier (persistent kernel) ----------------
// gpu-scope __threadfence() emits CCTL.IVALL on sm_103a -> L1 invalidated,
// so post-barrier loads of g_h observe remote SMs' writes via L2.
__device__ __forceinline__ void grid_barrier(unsigned nb)
{
    __syncthreads();
    if (threadIdx.x == 0) {
        __threadfence();                       // publish our writes + invalidate L1
        volatile unsigned* vgen = &g_gen;
        unsigned g = *vgen;
        if (atomicAdd(&g_cnt, 1u) == nb - 1u) {
            g_cnt = 0u;
            __threadfence();
            *vgen = g + 1u;                    // release
        } else {
            while (*vgen == g) { }             // spin (one thread per block)
            __threadfence();                   // acquire + L1 invalidate
        }
    }
    __syncthreads();
}

// ---------------- wavefront RNN kernel ----------------
// wave w: layer l computes t = w - l.  One barrier per wave.
__global__ __launch_bounds__(1024, 1) void rnn_wave_kernel(
    const float* __restrict__ Wh,    // [4, 2048, 2048]
    const float* __restrict__ Whh,   // [3, 2048, 2048]
    const float* __restrict__ Bh,    // [4, 2048]
    float*                    hfinal_out) // d_out + SEQ*INSZ (or null)
{
    const unsigned nb  = gridDim.x;
    const int gtid     = blockIdx.x * 1024 + threadIdx.x;
    const int nthreads = (int)nb * 1024;

    // zero hidden state (must happen every launch: graph replays reuse g_h)
    for (int i = gtid; i < NL * 2 * HID; i += nthreads)
        ((float*)g_h)[i] = 0.f;
    grid_barrier(nb);

    const int lane  = threadIdx.x & 31;
    const int gw    = (blockIdx.x << 5) + (threadIdx.x >> 5);
    const int nwarp = (int)nb * 32;

    for (int w = 0; w < SEQ + NL - 1; ++w) {
        for (int task = gw; task < NL * HID; task += nwarp) {
            const int l = task & 3;       // interleave layers across warps/blocks
            const int r = task >> 2;
            const int t = w - l;
            if ((unsigned)t < (unsigned)SEQ) {
                const float4* wrow = (const float4*)(Wh + ((size_t)l * HID + r) * HID);
                const float4* hp   = (const float4*)(g_h[l][(t - 1) & 1]);
                float ax = 0.f, ay = 0.f, az = 0.f, aw = 0.f;
                #pragma unroll
                for (int i = 0; i < 16; ++i) {
                    float4 a = wrow[lane + 32 * i];
                    float4 b = hp[lane + 32 * i];
                    ax = fmaf(a.x, b.x, ax); ay = fmaf(a.y, b.y, ay);
                    az = fmaf(a.z, b.z, az); aw = fmaf(a.w, b.w, aw);
                }
                if (l > 0) {
                    const float4* urow = (const float4*)(Whh + ((size_t)(l - 1) * HID + r) * HID);
                    const float4* hb   = (const float4*)(g_h[l - 1][t & 1]);
                    #pragma unroll
                    for (int i = 0; i < 16; ++i) {
                        float4 a = urow[lane + 32 * i];
                        float4 b = hb[lane + 32 * i];
                        ax = fmaf(a.x, b.x, ax); ay = fmaf(a.y, b.y, ay);
                        az = fmaf(a.z, b.z, az); aw = fmaf(a.w, b.w, aw);
                    }
                }
                float acc = (ax + ay) + (az + aw);
                #pragma unroll
                for (int s = 16; s; s >>= 1)
                    acc += __shfl_xor_sync(0xffffffffu, acc, s);
                if (lane == 0) {
                    acc += Bh[l * HID + r];
                    if (l == 0) acc += g_xin[(size_t)t * HID + r];
                    float hv = tanhf(acc);
                    g_h[l][t & 1][r] = hv;
                    if (l == 3) g_h3[(size_t)t * HID + r] = hv;
                }
            }
        }
        grid_barrier(nb);
    }

    // h_final = h(t=2047) -> parity 1
    if (hfinal_out) {
        for (int i = gtid; i < NL * HID; i += nthreads)
            hfinal_out[i] = g_h[i >> 11][1][i & (HID - 1)];
    }
}

// ---------------- generic C[M,N] = A[M,K] * B[N,K]^T (+bias) ----------------
// 64x64 tile, 256 threads, 4x4 per-thread register tile, K-tile 16.
__global__ __launch_bounds__(256) void gemm_abt_kernel(
    const float* __restrict__ A,
    const float* __restrict__ B,
    float*       __restrict__ C,
    const float* __restrict__ bias,
    int M, int N, int K)
{
    __shared__ float As[16][68];
    __shared__ float Bs[16][68];

    const int tn  = blockIdx.x * 64;
    const int tm  = blockIdx.y * 64;
    const int tid = threadIdx.x;
    const int tx  = tid & 15;
    const int ty  = tid >> 4;
    const int lr  = tid >> 2;   // 0..63 (row within tile for loading)
    const int lq  = tid & 3;    // which float4 of the 16-wide K slab

    float acc[4][4];
    #pragma unroll
    for (int i = 0; i < 4; ++i)
        #pragma unroll
        for (int j = 0; j < 4; ++j) acc[i][j] = 0.f;

    for (int k0 = 0; k0 < K; k0 += 16) {
        float4 a4 = *(const float4*)(A + (size_t)(tm + lr) * K + k0 + lq * 4);
        float4 b4 = *(const float4*)(B + (size_t)(tn + lr) * K + k0 + lq * 4);
        As[lq * 4 + 0][lr] = a4.x; As[lq * 4 + 1][lr] = a4.y;
        As[lq * 4 + 2][lr] = a4.z; As[lq * 4 + 3][lr] = a4.w;
        Bs[lq * 4 + 0][lr] = b4.x; Bs[lq * 4 + 1][lr] = b4.y;
        Bs[lq * 4 + 2][lr] = b4.z; Bs[lq * 4 + 3][lr] = b4.w;
        __syncthreads();
        #pragma unroll
        for (int kk = 0; kk < 16; ++kk) {
            float a0 = As[kk][ty * 4 + 0], a1 = As[kk][ty * 4 + 1];
            float a2 = As[kk][ty * 4 + 2], a3 = As[kk][ty * 4 + 3];
            float b0 = Bs[kk][tx * 4 + 0], b1 = Bs[kk][tx * 4 + 1];
            float b2 = Bs[kk][tx * 4 + 2], b3 = Bs[kk][tx * 4 + 3];
            acc[0][0] = fmaf(a0, b0, acc[0][0]); acc[0][1] = fmaf(a0, b1, acc[0][1]);
            acc[0][2] = fmaf(a0, b2, acc[0][2]); acc[0][3] = fmaf(a0, b3, acc[0][3]);
            acc[1][0] = fmaf(a1, b0, acc[1][0]); acc[1][1] = fmaf(a1, b1, acc[1][1]);
            acc[1][2] = fmaf(a1, b2, acc[1][2]); acc[1][3] = fmaf(a1, b3, acc[1][3]);
            acc[2][0] = fmaf(a2, b0, acc[2][0]); acc[2][1] = fmaf(a2, b1, acc[2][1]);
            acc[2][2] = fmaf(a2, b2, acc[2][2]); acc[2][3] = fmaf(a2, b3, acc[2][3]);
            acc[3][0] = fmaf(a3, b0, acc[3][0]); acc[3][1] = fmaf(a3, b1, acc[3][1]);
            acc[3][2] = fmaf(a3, b2, acc[3][2]); acc[3][3] = fmaf(a3, b3, acc[3][3]);
        }
        __syncthreads();
    }

    #pragma unroll
    for (int i = 0; i < 4; ++i) {
        const int row = tm + ty * 4 + i;
        #pragma unroll
        for (int j = 0; j < 4; ++j) {
            const int col = tn + tx * 4 + j;
            float v = acc[i][j];
            if (bias) v += bias[col];
            C[(size_t)row * N + col] = v;
        }
    }
}

// ---------------- launch ----------------
extern "C" void kernel_launch(void* const* d_in, const int* in_sizes, int n_in,
                              void* d_out, int out_size)
{
    const float* x   = (const float*)d_in[0]; // [2048,1024]
    const float* Wh  = (const float*)d_in[1]; // [4,2048,2048]
    const float* Whh = (const float*)d_in[2]; // [3,2048,2048]
    const float* Wx  = (const float*)d_in[3]; // [2048,1024]
    const float* Wy  = (const float*)d_in[4]; // [1024,2048]
    const float* Bh  = (const float*)d_in[5]; // [4,2048]
    const float* By  = (const float*)d_in[6]; // [1024]
    float* out = (float*)d_out;

    (void)in_sizes; (void)n_in;

    void* p_xin = nullptr;
    void* p_h3  = nullptr;
    cudaGetSymbolAddress(&p_xin, g_xin);
    cudaGetSymbolAddress(&p_h3,  g_h3);

    int nsm = 0;
    cudaDeviceGetAttribute(&nsm, cudaDevAttrMultiProcessorCount, 0);
    if (nsm <= 0) nsm = 148;

    // 1) xin = x @ Wx^T   : M=SEQ, N=HID, K=INSZ
    {
        dim3 grid(HID / 64, SEQ / 64);
        gemm_abt_kernel<<<grid, 256>>>(x, Wx, (float*)p_xin, nullptr,
                                       SEQ, HID, INSZ);
    }

    // 2) wavefront recurrence (persistent kernel, grid = #SMs)
    {
        float* hfinal = nullptr;
        if (out_size >= SEQ * INSZ + NL * HID)
            hfinal = out + (size_t)SEQ * INSZ;
        rnn_wave_kernel<<<nsm, 1024>>>(Wh, Whh, Bh, hfinal);
    }

    // 3) ys = h3_all @ Wy^T + By : M=SEQ, N=INSZ, K=HID
    {
        dim3 grid(INSZ / 64, SEQ / 64);
        gemm_abt_kernel<<<grid, 256>>>((const float*)p_h3, Wy, out, By,
                                       SEQ, INSZ, HID);
    }
}

// round 2
// speedup vs baseline: 1.0800x; 1.0800x over previous
#include <cuda_runtime.h>
#include <math.h>
#include <stdint.h>

#define SEQ   2048
#define HID   2048
#define INSZ  1024
#define NL    4
#define NMAT  7                   // 4 W_h dots + 3 W_hh dots per timestep
#define SENT  0xFFFFFFFFu         // NaN bit pattern; partials are always finite

// ---------------- persistent device scratch ----------------
__device__ float    g_h[NL][2][HID];          // double-buffered hidden states
__device__ float    g_xin[(size_t)SEQ * HID]; // x @ W_x^T
__device__ float    g_h3[(size_t)SEQ * HID];  // h3(t) for all t (feeds y GEMM)
__device__ unsigned g_slot[3 * HID];          // exch slots for layers 1..3
__device__ unsigned g_cnt = 0;
__device__ unsigned g_gen = 0;

// ---------------- grid-wide barrier (persistent kernel) ----------------
__device__ __forceinline__ void grid_barrier(unsigned nb)
{
    __syncthreads();
    if (threadIdx.x == 0) {
        __threadfence();                       // publish writes (+ L1 inval)
        volatile unsigned* vgen = &g_gen;
        unsigned g = *vgen;
        if (atomicAdd(&g_cnt, 1u) == nb - 1u) {
            g_cnt = 0u;
            __threadfence();
            *vgen = g + 1u;                    // release
        } else {
            while (*vgen == g) { }             // spin (one thread per block)
            __threadfence();                   // acquire (+ L1 inval)
        }
    }
    __syncthreads();
}

// ---------------- wavefront RNN kernel ----------------
// wave w: layer l computes timestep t = w - l. One barrier per wave.
// Work unit = ONE matrix-row dot (8KB). l>0 rows are two units (Wh part,
// Whh part) combined via atomicExch sentinel protocol: second arriver sums,
// activates, stores h.
__global__ __launch_bounds__(1024, 1) void rnn_wave_kernel(
    const float* __restrict__ Wh,    // [4, 2048, 2048]
    const float* __restrict__ Whh,   // [3, 2048, 2048]
    const float* __restrict__ Bh,    // [4, 2048]
    float*                    hfinal_out)
{
    __shared__ float sm_h[NL][HID];  // 32KB: h buffers consumed this wave

    const unsigned nb  = gridDim.x;
    const int tid      = threadIdx.x;
    const int gtid     = blockIdx.x * 1024 + tid;
    const int nthreads = (int)nb * 1024;

    // per-launch init (graph replays reuse device globals)
    for (int i = gtid; i < NL * 2 * HID; i += nthreads)
        ((float*)g_h)[i] = 0.f;
    for (int i = gtid; i < 3 * HID; i += nthreads)
        g_slot[i] = SENT;
    grid_barrier(nb);

    const int lane  = tid & 31;
    const int gw    = (blockIdx.x << 5) + (tid >> 5);
    const int nwarp = (int)nb * 32;

    for (int w = 0; w < SEQ + NL - 1; ++w) {
        // Stage the 4 h-buffers this wave reads into smem (L1-bypass loads).
        // Wh[l] reads h[l](t-1) = g_h[l][(w+l+1)&1]; Whh[l-1] reads the same
        // buffer of layer l-1, so exactly 4 vectors are needed.
        for (int i = tid; i < NL * HID / 4; i += 1024) {
            const int l = i >> 9;          // HID/4 = 512 float4 per layer
            const int j = i & 511;
            const float4 v = __ldcg((const float4*)g_h[l][(w + l + 1) & 1] + j);
            ((float4*)sm_h[l])[j] = v;
        }
        __syncthreads();

        for (int u = gw; u < NMAT * HID; u += nwarp) {
            const int m = u % NMAT;
            const int r = u / NMAT;
            int l, hsrc;
            const float* wrow;
            if (m < 4) {                    // W_h[m] · h_m(t-1)
                l = m; hsrc = m;
                wrow = Wh + ((size_t)m * HID + r) * HID;
            } else {                        // W_hh[m-4] · h_{m-4}(t)
                l = m - 3; hsrc = m - 4;
                wrow = Whh + ((size_t)(m - 4) * HID + r) * HID;
            }
            const int t = w - l;
            if ((unsigned)t >= (unsigned)SEQ) continue;

            const float4* w4 = (const float4*)wrow;
            const float4* h4 = (const float4*)sm_h[hsrc];
            float ax = 0.f, ay = 0.f, az = 0.f, aw = 0.f;
            #pragma unroll
            for (int i = 0; i < 16; ++i) {
                float4 a = w4[lane + 32 * i];
                float4 b = h4[lane + 32 * i];
                ax = fmaf(a.x, b.x, ax); ay = fmaf(a.y, b.y, ay);
                az = fmaf(a.z, b.z, az); aw = fmaf(a.w, b.w, aw);
            }
            float acc = (ax + ay) + (az + aw);
            #pragma unroll
            for (int s = 16; s; s >>= 1)
                acc += __shfl_xor_sync(0xffffffffu, acc, s);

            if (lane == 0) {
                if (m == 0) {
                    // layer 0: single contributor, finish directly
                    float v = acc + Bh[r] + g_xin[(size_t)t * HID + r];
                    g_h[0][t & 1][r] = tanhf(v);
                } else {
                    float p = acc + ((m < 4) ? Bh[l * HID + r] : 0.f);
                    unsigned* slot = &g_slot[(l - 1) * HID + r];
                    unsigned old = atomicExch(slot, __float_as_uint(p));
                    if (old != SENT) {       // I'm second: combine & finish
                        float tot = p + __uint_as_float(old);
                        *slot = SENT;        // self-reset for next wave
                        float hv = tanhf(tot);
                        g_h[l][t & 1][r] = hv;
                        if (l == 3) g_h3[(size_t)t * HID + r] = hv;
                    }
                }
            }
        }
        grid_barrier(nb);
    }

    // h_final = h(t=2047) lives in parity 1
    if (hfinal_out) {
        for (int i = gtid; i < NL * HID; i += nthreads)
            hfinal_out[i] = __ldcg(&g_h[i >> 11][1][i & (HID - 1)]);
    }
}

// ---------------- generic C[M,N] = A[M,K] * B[N,K]^T (+bias) ----------------
__global__ __launch_bounds__(256) void gemm_abt_kernel(
    const float* __restrict__ A,
    const float* __restrict__ B,
    float*       __restrict__ C,
    const float* __restrict__ bias,
    int M, int N, int K)
{
    __shared__ float As[16][68];
    __shared__ float Bs[16][68];

    const int tn  = blockIdx.x * 64;
    const int tm  = blockIdx.y * 64;
    const int tid = threadIdx.x;
    const int tx  = tid & 15;
    const int ty  = tid >> 4;
    const int lr  = tid >> 2;
    const int lq  = tid & 3;

    float acc[4][4];
    #pragma unroll
    for (int i = 0; i < 4; ++i)
        #pragma unroll
        for (int j = 0; j < 4; ++j) acc[i][j] = 0.f;

    for (int k0 = 0; k0 < K; k0 += 16) {
        float4 a4 = *(const float4*)(A + (size_t)(tm + lr) * K + k0 + lq * 4);
        float4 b4 = *(const float4*)(B + (size_t)(tn + lr) * K + k0 + lq * 4);
        As[lq * 4 + 0][lr] = a4.x; As[lq * 4 + 1][lr] = a4.y;
        As[lq * 4 + 2][lr] = a4.z; As[lq * 4 + 3][lr] = a4.w;
        Bs[lq * 4 + 0][lr] = b4.x; Bs[lq * 4 + 1][lr] = b4.y;
        Bs[lq * 4 + 2][lr] = b4.z; Bs[lq * 4 + 3][lr] = b4.w;
        __syncthreads();
        #pragma unroll
        for (int kk = 0; kk < 16; ++kk) {
            float a0 = As[kk][ty * 4 + 0], a1 = As[kk][ty * 4 + 1];
            float a2 = As[kk][ty * 4 + 2], a3 = As[kk][ty * 4 + 3];
            float b0 = Bs[kk][tx * 4 + 0], b1 = Bs[kk][tx * 4 + 1];
            float b2 = Bs[kk][tx * 4 + 2], b3 = Bs[kk][tx * 4 + 3];
            acc[0][0] = fmaf(a0, b0, acc[0][0]); acc[0][1] = fmaf(a0, b1, acc[0][1]);
            acc[0][2] = fmaf(a0, b2, acc[0][2]); acc[0][3] = fmaf(a0, b3, acc[0][3]);
            acc[1][0] = fmaf(a1, b0, acc[1][0]); acc[1][1] = fmaf(a1, b1, acc[1][1]);
            acc[1][2] = fmaf(a1, b2, acc[1][2]); acc[1][3] = fmaf(a1, b3, acc[1][3]);
            acc[2][0] = fmaf(a2, b0, acc[2][0]); acc[2][1] = fmaf(a2, b1, acc[2][1]);
            acc[2][2] = fmaf(a2, b2, acc[2][2]); acc[2][3] = fmaf(a2, b3, acc[2][3]);
            acc[3][0] = fmaf(a3, b0, acc[3][0]); acc[3][1] = fmaf(a3, b1, acc[3][1]);
            acc[3][2] = fmaf(a3, b2, acc[3][2]); acc[3][3] = fmaf(a3, b3, acc[3][3]);
        }
        __syncthreads();
    }

    #pragma unroll
    for (int i = 0; i < 4; ++i) {
        const int row = tm + ty * 4 + i;
        #pragma unroll
        for (int j = 0; j < 4; ++j) {
            const int col = tn + tx * 4 + j;
            float v = acc[i][j];
            if (bias) v += bias[col];
            C[(size_t)row * N + col] = v;
        }
    }
}

// ---------------- launch ----------------
extern "C" void kernel_launch(void* const* d_in, const int* in_sizes, int n_in,
                              void* d_out, int out_size)
{
    const float* x   = (const float*)d_in[0]; // [2048,1024]
    const float* Wh  = (const float*)d_in[1]; // [4,2048,2048]
    const float* Whh = (const float*)d_in[2]; // [3,2048,2048]
    const float* Wx  = (const float*)d_in[3]; // [2048,1024]
    const float* Wy  = (const float*)d_in[4]; // [1024,2048]
    const float* Bh  = (const float*)d_in[5]; // [4,2048]
    const float* By  = (const float*)d_in[6]; // [1024]
    float* out = (float*)d_out;

    (void)in_sizes; (void)n_in;

    void* p_xin = nullptr;
    void* p_h3  = nullptr;
    cudaGetSymbolAddress(&p_xin, g_xin);
    cudaGetSymbolAddress(&p_h3,  g_h3);

    int nsm = 0;
    cudaDeviceGetAttribute(&nsm, cudaDevAttrMultiProcessorCount, 0);
    if (nsm <= 0) nsm = 148;

    // 1) xin = x @ Wx^T : [SEQ, HID]
    {
        dim3 grid(HID / 64, SEQ / 64);
        gemm_abt_kernel<<<grid, 256>>>(x, Wx, (float*)p_xin, nullptr,
                                       SEQ, HID, INSZ);
    }

    // 2) wavefront recurrence (persistent kernel, grid = #SMs)
    {
        float* hfinal = nullptr;
        if (out_size >= SEQ * INSZ + NL * HID)
            hfinal = out + (size_t)SEQ * INSZ;
        rnn_wave_kernel<<<nsm, 1024>>>(Wh, Whh, Bh, hfinal);
    }

    // 3) ys = h3_all @ Wy^T + By : [SEQ, INSZ]
    {
        dim3 grid(INSZ / 64, SEQ / 64);
        gemm_abt_kernel<<<grid, 256>>>((const float*)p_h3, Wy, out, By,
                                       SEQ, INSZ, HID);
    }
}

// round 3
// speedup vs baseline: 1.5843x; 1.4669x over previous
#include <cuda_runtime.h>
#include <cuda_fp16.h>
#include <math.h>
#include <stdint.h>

#define SEQ   2048
#define HID   2048
#define INSZ  1024
#define NL    4
#define NMAT  7                   // 4 W_h dots + 3 W_hh dots per timestep
#define SENT  0xFFFFFFFFu
#define NW4   ((size_t)4 * HID * HID)    // elements in Wh
#define NTOT  ((size_t)7 * HID * HID)    // elements in Wh+Whh

// ---------------- persistent device scratch ----------------
__device__ __half   g_w16[NTOT];              // fp16 weights: [Wh(4) | Whh(3)]
__device__ float    g_h[NL][2][HID];          // double-buffered hidden states
__device__ float    g_xin[(size_t)SEQ * HID]; // x @ W_x^T
__device__ float    g_h3[(size_t)SEQ * HID];  // h3(t) for all t
__device__ unsigned g_slot[3 * HID];          // exch slots for layers 1..3
__device__ unsigned g_cnt = 0;
__device__ unsigned g_gen = 0;

// ---------------- weight conversion fp32 -> fp16 ----------------
__global__ void convert_w_kernel(const float* __restrict__ Wh,
                                 const float* __restrict__ Whh)
{
    const size_t n4 = NTOT / 4;
    const size_t nw4 = NW4 / 4;
    for (size_t i = (size_t)blockIdx.x * blockDim.x + threadIdx.x;
         i < n4; i += (size_t)gridDim.x * blockDim.x) {
        float4 v = (i < nw4) ? ((const float4*)Wh)[i]
                             : ((const float4*)Whh)[i - nw4];
        __half2* dst = (__half2*)g_w16 + 2 * i;
        dst[0] = __floats2half2_rn(v.x, v.y);
        dst[1] = __floats2half2_rn(v.z, v.w);
    }
}

// ---------------- grid-wide barrier (persistent kernel) ----------------
__device__ __forceinline__ void grid_barrier(unsigned nb)
{
    __syncthreads();
    if (threadIdx.x == 0) {
        __threadfence();
        volatile unsigned* vgen = &g_gen;
        unsigned g = *vgen;
        if (atomicAdd(&g_cnt, 1u) == nb - 1u) {
            g_cnt = 0u;
            __threadfence();
            *vgen = g + 1u;
        } else {
            while (*vgen == g) { }
            __threadfence();
        }
    }
    __syncthreads();
}

// ---------------- wavefront RNN kernel ----------------
// wave w: layer l computes timestep t = w - l. One barrier per wave.
// Work unit = one fp16 matrix-row dot (4KB). Stable warp->unit permutation
// preserves within-launch L1 reuse; units with (u%7)<3 use caching loads
// (~166KB/SM pinned in L1), the rest stream via __ldcg.
__global__ __launch_bounds__(1024, 1) void rnn_wave_kernel(
    const float* __restrict__ Bh,
    float*                    hfinal_out)
{
    __shared__ float sm_h[NL][HID];   // 32KB
    __shared__ float sm_xin[HID];     // 8KB

    const unsigned nb  = gridDim.x;
    const int tid      = threadIdx.x;
    const int gtid     = blockIdx.x * 1024 + tid;
    const int nthreads = (int)nb * 1024;

    for (int i = gtid; i < NL * 2 * HID; i += nthreads)
        ((float*)g_h)[i] = 0.f;
    for (int i = gtid; i < 3 * HID; i += nthreads)
        g_slot[i] = SENT;
    grid_barrier(nb);

    const int lane  = tid & 31;
    const int gw    = (blockIdx.x << 5) + (tid >> 5);
    const int nwarp = (int)nb * 32;
    // stable permuted warp id: spreads the 128 "extra-unit" warps ~1/block
    const int swid  = (int)(((long long)gw * 149) % nwarp);

    for (int w = 0; w < SEQ + NL - 1; ++w) {
        // stage the 4 h-buffers this wave reads + xin row for t=w
        for (int i = tid; i < NL * (HID / 4); i += 1024) {
            const int l = i >> 9;
            const int j = i & 511;
            ((float4*)sm_h[l])[j] =
                __ldcg((const float4*)g_h[l][(w + l + 1) & 1] + j);
        }
        if (tid < HID / 4 && w < SEQ)
            ((float4*)sm_xin)[tid] =
                __ldcg((const float4*)(g_xin + (size_t)w * HID) + tid);
        __syncthreads();

        for (int u = swid; u < NMAT * HID; u += nwarp) {
            const int m = u % NMAT;
            const int r = u / NMAT;
            int l, hsrc;
            size_t wbase;
            if (m < 4) {                    // W_h[m] . h_m(t-1)
                l = m; hsrc = m;
                wbase = ((size_t)m * HID + r) * HID;
            } else {                        // W_hh[m-4] . h_{m-4}(t)
                l = m - 3; hsrc = m - 4;
                wbase = NW4 + ((size_t)(m - 4) * HID + r) * HID;
            }
            const int t = w - l;
            if ((unsigned)t >= (unsigned)SEQ) continue;

            const uint4*  w4 = (const uint4*)(g_w16 + wbase);
            const float4* h4 = (const float4*)sm_h[hsrc];
            float ax = 0.f, ay = 0.f, az = 0.f, aw = 0.f;

            if (u % 7 < 3) {
                // L1-pinned path (caching loads; stable set per SM)
                #pragma unroll
                for (int i = 0; i < 8; ++i) {
                    const int idx = lane + 32 * i;
                    uint4  wv = w4[idx];
                    float4 h0 = h4[2 * idx];
                    float4 h1 = h4[2 * idx + 1];
                    float2 c;
                    c = __half22float2(*(__half2*)&wv.x);
                    ax = fmaf(c.x, h0.x, ax); ay = fmaf(c.y, h0.y, ay);
                    c = __half22float2(*(__half2*)&wv.y);
                    az = fmaf(c.x, h0.z, az); aw = fmaf(c.y, h0.w, aw);
                    c = __half22float2(*(__half2*)&wv.z);
                    ax = fmaf(c.x, h1.x, ax); ay = fmaf(c.y, h1.y, ay);
                    c = __half22float2(*(__half2*)&wv.w);
                    az = fmaf(c.x, h1.z, az); aw = fmaf(c.y, h1.w, aw);
                }
            } else {
                // streaming path (L2-only, no L1 allocate)
                #pragma unroll
                for (int i = 0; i < 8; ++i) {
                    const int idx = lane + 32 * i;
                    uint4  wv = __ldcg(w4 + idx);
                    float4 h0 = h4[2 * idx];
                    float4 h1 = h4[2 * idx + 1];
                    float2 c;
                    c = __half22float2(*(__half2*)&wv.x);
                    ax = fmaf(c.x, h0.x, ax); ay = fmaf(c.y, h0.y, ay);
                    c = __half22float2(*(__half2*)&wv.y);
                    az = fmaf(c.x, h0.z, az); aw = fmaf(c.y, h0.w, aw);
                    c = __half22float2(*(__half2*)&wv.z);
                    ax = fmaf(c.x, h1.x, ax); ay = fmaf(c.y, h1.y, ay);
                    c = __half22float2(*(__half2*)&wv.w);
                    az = fmaf(c.x, h1.z, az); aw = fmaf(c.y, h1.w, aw);
                }
            }

            float acc = (ax + ay) + (az + aw);
            #pragma unroll
            for (int s = 16; s; s >>= 1)
                acc += __shfl_xor_sync(0xffffffffu, acc, s);

            if (lane == 0) {
                if (m == 0) {
                    float v = acc + Bh[r] + sm_xin[r];
                    g_h[0][t & 1][r] = tanhf(v);
                } else {
                    float p = acc + ((m < 4) ? Bh[l * HID + r] : 0.f);
                    unsigned* slot = &g_slot[(l - 1) * HID + r];
                    unsigned old = atomicExch(slot, __float_as_uint(p));
                    if (old != SENT) {
                        float tot = p + __uint_as_float(old);
                        *slot = SENT;
                        float hv = tanhf(tot);
                        g_h[l][t & 1][r] = hv;
                        if (l == 3) g_h3[(size_t)t * HID + r] = hv;
                    }
                }
            }
        }
        grid_barrier(nb);
    }

    if (hfinal_out) {
        for (int i = gtid; i < NL * HID; i += nthreads)
            hfinal_out[i] = __ldcg(&g_h[i >> 11][1][i & (HID - 1)]);
    }
}

// ---------------- generic C[M,N] = A[M,K] * B[N,K]^T (+bias) ----------------
__global__ __launch_bounds__(256) void gemm_abt_kernel(
    const float* __restrict__ A,
    const float* __restrict__ B,
    float*       __restrict__ C,
    const float* __restrict__ bias,
    int M, int N, int K)
{
    __shared__ float As[16][68];
    __shared__ float Bs[16][68];

    const int tn  = blockIdx.x * 64;
    const int tm  = blockIdx.y * 64;
    const int tid = threadIdx.x;
    const int tx  = tid & 15;
    const int ty  = tid >> 4;
    const int lr  = tid >> 2;
    const int lq  = tid & 3;

    float acc[4][4];
    #pragma unroll
    for (int i = 0; i < 4; ++i)
        #pragma unroll
        for (int j = 0; j < 4; ++j) acc[i][j] = 0.f;

    for (int k0 = 0; k0 < K; k0 += 16) {
        float4 a4 = *(const float4*)(A + (size_t)(tm + lr) * K + k0 + lq * 4);
        float4 b4 = *(const float4*)(B + (size_t)(tn + lr) * K + k0 + lq * 4);
        As[lq * 4 + 0][lr] = a4.x; As[lq * 4 + 1][lr] = a4.y;
        As[lq * 4 + 2][lr] = a4.z; As[lq * 4 + 3][lr] = a4.w;
        Bs[lq * 4 + 0][lr] = b4.x; Bs[lq * 4 + 1][lr] = b4.y;
        Bs[lq * 4 + 2][lr] = b4.z; Bs[lq * 4 + 3][lr] = b4.w;
        __syncthreads();
        #pragma unroll
        for (int kk = 0; kk < 16; ++kk) {
            float a0 = As[kk][ty * 4 + 0], a1 = As[kk][ty * 4 + 1];
            float a2 = As[kk][ty * 4 + 2], a3 = As[kk][ty * 4 + 3];
            float b0 = Bs[kk][tx * 4 + 0], b1 = Bs[kk][tx * 4 + 1];
            float b2 = Bs[kk][tx * 4 + 2], b3 = Bs[kk][tx * 4 + 3];
            acc[0][0] = fmaf(a0, b0, acc[0][0]); acc[0][1] = fmaf(a0, b1, acc[0][1]);
            acc[0][2] = fmaf(a0, b2, acc[0][2]); acc[0][3] = fmaf(a0, b3, acc[0][3]);
            acc[1][0] = fmaf(a1, b0, acc[1][0]); acc[1][1] = fmaf(a1, b1, acc[1][1]);
            acc[1][2] = fmaf(a1, b2, acc[1][2]); acc[1][3] = fmaf(a1, b3, acc[1][3]);
            acc[2][0] = fmaf(a2, b0, acc[2][0]); acc[2][1] = fmaf(a2, b1, acc[2][1]);
            acc[2][2] = fmaf(a2, b2, acc[2][2]); acc[2][3] = fmaf(a2, b3, acc[2][3]);
            acc[3][0] = fmaf(a3, b0, acc[3][0]); acc[3][1] = fmaf(a3, b1, acc[3][1]);
            acc[3][2] = fmaf(a3, b2, acc[3][2]); acc[3][3] = fmaf(a3, b3, acc[3][3]);
        }
        __syncthreads();
    }

    #pragma unroll
    for (int i = 0; i < 4; ++i) {
        const int row = tm + ty * 4 + i;
        #pragma unroll
        for (int j = 0; j < 4; ++j) {
            const int col = tn + tx * 4 + j;
            float v = acc[i][j];
            if (bias) v += bias[col];
            C[(size_t)row * N + col] = v;
        }
    }
}

// ---------------- launch ----------------
extern "C" void kernel_launch(void* const* d_in, const int* in_sizes, int n_in,
                              void* d_out, int out_size)
{
    const float* x   = (const float*)d_in[0];
    const float* Wh  = (const float*)d_in[1];
    const float* Whh = (const float*)d_in[2];
    const float* Wx  = (const float*)d_in[3];
    const float* Wy  = (const float*)d_in[4];
    const float* Bh  = (const float*)d_in[5];
    const float* By  = (const float*)d_in[6];
    float* out = (float*)d_out;

    (void)in_sizes; (void)n_in;

    void* p_xin = nullptr;
    void* p_h3  = nullptr;
    cudaGetSymbolAddress(&p_xin, g_xin);
    cudaGetSymbolAddress(&p_h3,  g_h3);

    int nsm = 0;
    cudaDeviceGetAttribute(&nsm, cudaDevAttrMultiProcessorCount, 0);
    if (nsm <= 0) nsm = 148;

    // 0) fp32 -> fp16 weight conversion
    convert_w_kernel<<<nsm * 8, 256>>>(Wh, Whh);

    // 1) xin = x @ Wx^T : [SEQ, HID]
    {
        dim3 grid(HID / 64, SEQ / 64);
        gemm_abt_kernel<<<grid, 256>>>(x, Wx, (float*)p_xin, nullptr,
                                       SEQ, HID, INSZ);
    }

    // 2) wavefront recurrence (persistent kernel, grid = #SMs)
    {
        float* hfinal = nullptr;
        if (out_size >= SEQ * INSZ + NL * HID)
            hfinal = out + (size_t)SEQ * INSZ;
        rnn_wave_kernel<<<nsm, 1024>>>(Bh, hfinal);
    }

    // 3) ys = h3_all @ Wy^T + By : [SEQ, INSZ]
    {
        dim3 grid(INSZ / 64, SEQ / 64);
        gemm_abt_kernel<<<grid, 256>>>((const float*)p_h3, Wy, out, By,
                                       SEQ, INSZ, HID);
    }
}

// round 6
// speedup vs baseline: 1.6952x; 1.0700x over previous
#include <cuda_runtime.h>
#include <cuda_fp16.h>
#include <math.h>
#include <stdint.h>

#define SEQ   2048
#define HID   2048
#define INSZ  1024
#define NL    4
#define NMAT  7
#define SENT  0xFFFFFFFFu
#define NW4   ((size_t)4 * HID * HID)
#define NTOT  ((size_t)7 * HID * HID)
#define NCTR  8

// ---------------- persistent device scratch ----------------
__device__ __half   g_w16[NTOT];
__device__ float    g_h[NL][2][HID];
__device__ float    g_xin[(size_t)SEQ * HID];
__device__ float    g_h3[(size_t)SEQ * HID];
__device__ unsigned g_slot[3 * HID];
__device__ unsigned g_ctr[NCTR * 64];     // 8 arrival counters, 256B apart
__device__ unsigned g_cnt = 0;            // legacy init barrier
__device__ unsigned g_gen = 0;

// ---------------- scoped strong-op helpers (no CCTL.IVALL) ----------------
__device__ __forceinline__ void st_relaxed_f32(float* p, float v) {
    asm volatile("st.relaxed.gpu.global.f32 [%0], %1;" :: "l"(p), "f"(v));
}
__device__ __forceinline__ void st_relaxed_u32(unsigned* p, unsigned v) {
    asm volatile("st.relaxed.gpu.global.u32 [%0], %1;" :: "l"(p), "r"(v));
}
__device__ __forceinline__ unsigned ld_acquire_u32(const unsigned* p) {
    unsigned v;
    asm volatile("ld.acquire.gpu.global.u32 %0, [%1];" : "=r"(v) : "l"(p));
    return v;
}
__device__ __forceinline__ void red_release_add(unsigned* p, unsigned v) {
    asm volatile("red.release.gpu.global.add.u32 [%0], %1;" :: "l"(p), "r"(v));
}

// ---------------- weight conversion fp32 -> fp16 ----------------
__global__ void convert_w_kernel(const float* __restrict__ Wh,
                                 const float* __restrict__ Whh)
{
    const size_t n4  = NTOT / 4;
    const size_t nw4 = NW4 / 4;
    for (size_t i = (size_t)blockIdx.x * blockDim.x + threadIdx.x;
         i < n4; i += (size_t)gridDim.x * blockDim.x) {
        float4 v = (i < nw4) ? ((const float4*)Wh)[i]
                             : ((const float4*)Whh)[i - nw4];
        __half2* dst = (__half2*)g_w16 + 2 * i;
        dst[0] = __floats2half2_rn(v.x, v.y);
        dst[1] = __floats2half2_rn(v.z, v.w);
    }
}

// ---------------- legacy fenced barrier (init only; one IVALL is fine) ---
__device__ __forceinline__ void init_barrier(unsigned nb)
{
    __syncthreads();
    if (threadIdx.x == 0) {
        __threadfence();
        volatile unsigned* vgen = &g_gen;
        unsigned g = *vgen;
        if (atomicAdd(&g_cnt, 1u) == nb - 1u) {
            g_cnt = 0u;
            __threadfence();
            *vgen = g + 1u;
        } else {
            while (*vgen == g) { }
            __threadfence();
        }
    }
    __syncthreads();
}

// ---------------- IVALL-free wave barrier (release/acquire) ----------------
// __syncthreads gives happens-before from every warp's strong stores to
// thread 0; red.release (cumulative) publishes them; pollers use acquire
// loads. No fence instruction => no CCTL.IVALL => L1-pinned weights live.
__device__ __forceinline__ void wave_barrier(unsigned nb, unsigned epoch)
{
    __syncthreads();
    if (threadIdx.x == 0)
        red_release_add(&g_ctr[(blockIdx.x & (NCTR - 1)) * 64], 1u);
    if (threadIdx.x < NCTR) {
        const unsigned i = threadIdx.x;
        const unsigned per = (nb - i + NCTR - 1) / NCTR;  // #blocks, bid%8==i
        const unsigned target = per * epoch;
        while (ld_acquire_u32(&g_ctr[i * 64]) < target) { }
    }
    __syncthreads();
}

// ---------------- wavefront RNN kernel ----------------
__global__ __launch_bounds__(1024, 1) void rnn_wave_kernel(
    const float* __restrict__ Bh,
    float*                    hfinal_out)
{
    __shared__ float sm_h[NL][HID];   // 32KB => ~196KB L1 left for pinning

    const unsigned nb  = gridDim.x;
    const int tid      = threadIdx.x;
    const int gtid     = blockIdx.x * 1024 + tid;
    const int nthreads = (int)nb * 1024;

    // per-launch init (graph replays reuse device globals)
    for (int i = gtid; i < NL * 2 * HID; i += nthreads)
        ((float*)g_h)[i] = 0.f;
    for (int i = gtid; i < 3 * HID; i += nthreads)
        g_slot[i] = SENT;
    for (int i = gtid; i < NCTR * 64; i += nthreads)
        g_ctr[i] = 0u;
    init_barrier(nb);

    const int lane  = tid & 31;
    const int gw    = (blockIdx.x << 5) + (tid >> 5);
    const int nwarp = (int)nb * 32;
    const int swid  = (int)(((long long)gw * 149) % nwarp);  // stable permutation

    unsigned epoch = 0;

    for (int w = 0; w < SEQ + NL - 1; ++w) {
        // stage the 4 h-buffers this wave reads (L2-only loads; data is
        // guaranteed in L2 by the previous wave's release/acquire barrier)
        for (int i = tid; i < NL * (HID / 4); i += 1024) {
            const int l = i >> 9;
            const int j = i & 511;
            ((float4*)sm_h[l])[j] =
                __ldcg((const float4*)g_h[l][(w + l + 1) & 1] + j);
        }
        __syncthreads();

        for (int u = swid; u < NMAT * HID; u += nwarp) {
            const int m = u % NMAT;
            const int r = u / NMAT;
            int l, hsrc;
            size_t wbase;
            if (m < 4) {
                l = m; hsrc = m;
                wbase = ((size_t)m * HID + r) * HID;
            } else {
                l = m - 3; hsrc = m - 4;
                wbase = NW4 + ((size_t)(m - 4) * HID + r) * HID;
            }
            const int t = w - l;
            if ((unsigned)t >= (unsigned)SEQ) continue;

            const uint4*  w4 = (const uint4*)(g_w16 + wbase);
            const float4* h4 = (const float4*)sm_h[hsrc];
            float ax = 0.f, ay = 0.f, az = 0.f, aw = 0.f;

            if (m < 3) {
                // L1-pinned path: caching loads; stable warp->unit map keeps
                // ~160KB/SM resident (everything else is .cg / strong-L2).
                #pragma unroll
                for (int i = 0; i < 8; ++i) {
                    const int idx = lane + 32 * i;
                    uint4  wv = w4[idx];
                    float4 h0 = h4[2 * idx];
                    float4 h1 = h4[2 * idx + 1];
                    float2 c;
                    c = __half22float2(*(__half2*)&wv.x);
                    ax = fmaf(c.x, h0.x, ax); ay = fmaf(c.y, h0.y, ay);
                    c = __half22float2(*(__half2*)&wv.y);
                    az = fmaf(c.x, h0.z, az); aw = fmaf(c.y, h0.w, aw);
                    c = __half22float2(*(__half2*)&wv.z);
                    ax = fmaf(c.x, h1.x, ax); ay = fmaf(c.y, h1.y, ay);
                    c = __half22float2(*(__half2*)&wv.w);
                    az = fmaf(c.x, h1.z, az); aw = fmaf(c.y, h1.w, aw);
                }
            } else {
                // streaming path: L2-only, no L1 allocate
                #pragma unroll
                for (int i = 0; i < 8; ++i) {
                    const int idx = lane + 32 * i;
                    uint4  wv = __ldcg(w4 + idx);
                    float4 h0 = h4[2 * idx];
                    float4 h1 = h4[2 * idx + 1];
                    float2 c;
                    c = __half22float2(*(__half2*)&wv.x);
                    ax = fmaf(c.x, h0.x, ax); ay = fmaf(c.y, h0.y, ay);
                    c = __half22float2(*(__half2*)&wv.y);
                    az = fmaf(c.x, h0.z, az); aw = fmaf(c.y, h0.w, aw);
                    c = __half22float2(*(__half2*)&wv.z);
                    ax = fmaf(c.x, h1.x, ax); ay = fmaf(c.y, h1.y, ay);
                    c = __half22float2(*(__half2*)&wv.w);
                    az = fmaf(c.x, h1.z, az); aw = fmaf(c.y, h1.w, aw);
                }
            }

            float acc = (ax + ay) + (az + aw);
            #pragma unroll
            for (int s = 16; s; s >>= 1)
                acc += __shfl_xor_sync(0xffffffffu, acc, s);

            if (lane == 0) {
                if (m == 0) {
                    float v = acc + Bh[r] + __ldcg(g_xin + (size_t)t * HID + r);
                    st_relaxed_f32(&g_h[0][t & 1][r], tanhf(v));
                } else {
                    float p = acc + ((m < 4) ? Bh[l * HID + r] : 0.f);
                    unsigned* slot = &g_slot[(l - 1) * HID + r];
                    unsigned old = atomicExch(slot, __float_as_uint(p));
                    if (old != SENT) {
                        float tot = p + __uint_as_float(old);
                        st_relaxed_u32(slot, SENT);
                        float hv = tanhf(tot);
                        st_relaxed_f32(&g_h[l][t & 1][r], hv);
                        if (l == 3) st_relaxed_f32(&g_h3[(size_t)t * HID + r], hv);
                    }
                }
            }
        }
        ++epoch;
        wave_barrier(nb, epoch);
    }

    if (hfinal_out) {
        for (int i = gtid; i < NL * HID; i += nthreads)
            hfinal_out[i] = __ldcg(&g_h[i >> 11][1][i & (HID - 1)]);
    }
}

// ---------------- generic C[M,N] = A[M,K] * B[N,K]^T (+bias) ----------------
__global__ __launch_bounds__(256) void gemm_abt_kernel(
    const float* __restrict__ A,
    const float* __restrict__ B,
    float*       __restrict__ C,
    const float* __restrict__ bias,
    int M, int N, int K)
{
    __shared__ float As[16][68];
    __shared__ float Bs[16][68];

    const int tn  = blockIdx.x * 64;
    const int tm  = blockIdx.y * 64;
    const int tid = threadIdx.x;
    const int tx  = tid & 15;
    const int ty  = tid >> 4;
    const int lr  = tid >> 2;
    const int lq  = tid & 3;

    float acc[4][4];
    #pragma unroll
    for (int i = 0; i < 4; ++i)
        #pragma unroll
        for (int j = 0; j < 4; ++j) acc[i][j] = 0.f;

    for (int k0 = 0; k0 < K; k0 += 16) {
        float4 a4 = *(const float4*)(A + (size_t)(tm + lr) * K + k0 + lq * 4);
        float4 b4 = *(const float4*)(B + (size_t)(tn + lr) * K + k0 + lq * 4);
        As[lq * 4 + 0][lr] = a4.x; As[lq * 4 + 1][lr] = a4.y;
        As[lq * 4 + 2][lr] = a4.z; As[lq * 4 + 3][lr] = a4.w;
        Bs[lq * 4 + 0][lr] = b4.x; Bs[lq * 4 + 1][lr] = b4.y;
        Bs[lq * 4 + 2][lr] = b4.z; Bs[lq * 4 + 3][lr] = b4.w;
        __syncthreads();
        #pragma unroll
        for (int kk = 0; kk < 16; ++kk) {
            float a0 = As[kk][ty * 4 + 0], a1 = As[kk][ty * 4 + 1];
            float a2 = As[kk][ty * 4 + 2], a3 = As[kk][ty * 4 + 3];
            float b0 = Bs[kk][tx * 4 + 0], b1 = Bs[kk][tx * 4 + 1];
            float b2 = Bs[kk][tx * 4 + 2], b3 = Bs[kk][tx * 4 + 3];
            acc[0][0] = fmaf(a0, b0, acc[0][0]); acc[0][1] = fmaf(a0, b1, acc[0][1]);
            acc[0][2] = fmaf(a0, b2, acc[0][2]); acc[0][3] = fmaf(a0, b3, acc[0][3]);
            acc[1][0] = fmaf(a1, b0, acc[1][0]); acc[1][1] = fmaf(a1, b1, acc[1][1]);
            acc[1][2] = fmaf(a1, b2, acc[1][2]); acc[1][3] = fmaf(a1, b3, acc[1][3]);
            acc[2][0] = fmaf(a2, b0, acc[2][0]); acc[2][1] = fmaf(a2, b1, acc[2][1]);
            acc[2][2] = fmaf(a2, b2, acc[2][2]); acc[2][3] = fmaf(a2, b3, acc[2][3]);
            acc[3][0] = fmaf(a3, b0, acc[3][0]); acc[3][1] = fmaf(a3, b1, acc[3][1]);
            acc[3][2] = fmaf(a3, b2, acc[3][2]); acc[3][3] = fmaf(a3, b3, acc[3][3]);
        }
        __syncthreads();
    }

    #pragma unroll
    for (int i = 0; i < 4; ++i) {
        const int row = tm + ty * 4 + i;
        #pragma unroll
        for (int j = 0; j < 4; ++j) {
            const int col = tn + tx * 4 + j;
            float v = acc[i][j];
            if (bias) v += bias[col];
            C[(size_t)row * N + col] = v;
        }
    }
}

// ---------------- launch ----------------
extern "C" void kernel_launch(void* const* d_in, const int* in_sizes, int n_in,
                              void* d_out, int out_size)
{
    const float* x   = (const float*)d_in[0];
    const float* Wh  = (const float*)d_in[1];
    const float* Whh = (const float*)d_in[2];
    const float* Wx  = (const float*)d_in[3];
    const float* Wy  = (const float*)d_in[4];
    const float* Bh  = (const float*)d_in[5];
    const float* By  = (const float*)d_in[6];
    float* out = (float*)d_out;

    (void)in_sizes; (void)n_in;

    void* p_xin = nullptr;
    void* p_h3  = nullptr;
    cudaGetSymbolAddress(&p_xin, g_xin);
    cudaGetSymbolAddress(&p_h3,  g_h3);

    int nsm = 0;
    cudaDeviceGetAttribute(&nsm, cudaDevAttrMultiProcessorCount, 0);
    if (nsm <= 0) nsm = 148;

    // prefer small smem carveout: maximize L1 for pinned weights (idempotent)
    cudaFuncSetAttribute(rnn_wave_kernel,
                         cudaFuncAttributePreferredSharedMemoryCarveout, 15);

    // 0) fp32 -> fp16 weight conversion
    convert_w_kernel<<<nsm * 8, 256>>>(Wh, Whh);

    // 1) xin = x @ Wx^T : [SEQ, HID]
    {
        dim3 grid(HID / 64, SEQ / 64);
        gemm_abt_kernel<<<grid, 256>>>(x, Wx, (float*)p_xin, nullptr,
                                       SEQ, HID, INSZ);
    }

    // 2) wavefront recurrence (persistent kernel, grid = #SMs)
    {
        float* hfinal = nullptr;
        if (out_size >= SEQ * INSZ + NL * HID)
            hfinal = out + (size_t)SEQ * INSZ;
        rnn_wave_kernel<<<nsm, 1024>>>(Bh, hfinal);
    }

    // 3) ys = h3_all @ Wy^T + By : [SEQ, INSZ]
    {
        dim3 grid(INSZ / 64, SEQ / 64);
        gemm_abt_kernel<<<grid, 256>>>((const float*)p_h3, Wy, out, By,
                                       SEQ, INSZ, HID);
    }
}

// round 8
// speedup vs baseline: 1.7911x; 1.0565x over previous
#include <cuda_runtime.h>
#include <cuda_fp16.h>
#include <math.h>
#include <stdint.h>

#define SEQ   2048
#define HID   2048
#define INSZ  1024
#define NL    4
#define NMAT  7
#define SENT  0xFFFFFFFFu
#define NW4   ((size_t)4 * HID * HID)
#define NTOT  ((size_t)7 * HID * HID)
#define NCTR  8
#define HU_TOTAL (14 * HID)          // 7 matrices * 2 K-halves * 2048 rows

// ---------------- persistent device scratch ----------------
__device__ __half   g_w16[NTOT];
__device__ float    g_h[NL][2][HID];
__device__ float    g_xin[(size_t)SEQ * HID];
__device__ float    g_h3[(size_t)SEQ * HID];
__device__ unsigned g_hslot[NMAT * HID];  // K-half merge slots
__device__ unsigned g_slot[3 * HID];      // cross-matrix merge slots
__device__ unsigned g_ctr[NCTR * 64];
__device__ unsigned g_cnt = 0;
__device__ unsigned g_gen = 0;

// ---------------- scoped strong-op helpers (no CCTL.IVALL) ----------------
__device__ __forceinline__ void st_relaxed_f32(float* p, float v) {
    asm volatile("st.relaxed.gpu.global.f32 [%0], %1;" :: "l"(p), "f"(v));
}
__device__ __forceinline__ void st_relaxed_u32(unsigned* p, unsigned v) {
    asm volatile("st.relaxed.gpu.global.u32 [%0], %1;" :: "l"(p), "r"(v));
}
__device__ __forceinline__ unsigned ld_acquire_u32(const unsigned* p) {
    unsigned v;
    asm volatile("ld.acquire.gpu.global.u32 %0, [%1];" : "=r"(v) : "l"(p));
    return v;
}
__device__ __forceinline__ void red_release_add(unsigned* p, unsigned v) {
    asm volatile("red.release.gpu.global.add.u32 [%0], %1;" :: "l"(p), "r"(v));
}

// ---------------- weight conversion fp32 -> fp16 ----------------
__global__ void convert_w_kernel(const float* __restrict__ Wh,
                                 const float* __restrict__ Whh)
{
    const size_t n4  = NTOT / 4;
    const size_t nw4 = NW4 / 4;
    for (size_t i = (size_t)blockIdx.x * blockDim.x + threadIdx.x;
         i < n4; i += (size_t)gridDim.x * blockDim.x) {
        float4 v = (i < nw4) ? ((const float4*)Wh)[i]
                             : ((const float4*)Whh)[i - nw4];
        __half2* dst = (__half2*)g_w16 + 2 * i;
        dst[0] = __floats2half2_rn(v.x, v.y);
        dst[1] = __floats2half2_rn(v.z, v.w);
    }
}

__global__ void noop_kernel() {}   // launch-order pad so ncu (4th exec) hits the wave kernel

// ---------------- legacy fenced barrier (init only) ----------------
__device__ __forceinline__ void init_barrier(unsigned nb)
{
    __syncthreads();
    if (threadIdx.x == 0) {
        __threadfence();
        volatile unsigned* vgen = &g_gen;
        unsigned g = *vgen;
        if (atomicAdd(&g_cnt, 1u) == nb - 1u) {
            g_cnt = 0u;
            __threadfence();
            *vgen = g + 1u;
        } else {
            while (*vgen == g) { }
            __threadfence();
        }
    }
    __syncthreads();
}

// ---------------- IVALL-free wave barrier (release/acquire, proven R6) ----
__device__ __forceinline__ void wave_barrier(unsigned nb, unsigned epoch)
{
    __syncthreads();
    if (threadIdx.x == 0)
        red_release_add(&g_ctr[(blockIdx.x & (NCTR - 1)) * 64], 1u);
    if (threadIdx.x < NCTR) {
        const unsigned i = threadIdx.x;
        const unsigned per = (nb - i + NCTR - 1) / NCTR;
        const unsigned target = per * epoch;
        while (ld_acquire_u32(&g_ctr[i * 64]) < target) { }
    }
    __syncthreads();
}

// ---------------- row-finish protocol (2-level exch-sentinel) ----------------
__device__ __forceinline__ void finish_row_partial(int m, int r, int t, int l,
                                                   float p, const float* __restrict__ Bh)
{
    unsigned* hs = &g_hslot[m * HID + r];
    unsigned old = atomicExch(hs, __float_as_uint(p));
    if (old == SENT) return;                 // first K-half arriver
    float full = p + __uint_as_float(old);
    st_relaxed_u32(hs, SENT);                // self-reset for next wave
    if (m == 0) {
        float v = full + Bh[r] + __ldcg(g_xin + (size_t)t * HID + r);
        st_relaxed_f32(&g_h[0][t & 1][r], tanhf(v));
    } else {
        float q = full + ((m < 4) ? Bh[m * HID + r] : 0.f);
        unsigned* cs = &g_slot[(l - 1) * HID + r];
        unsigned old2 = atomicExch(cs, __float_as_uint(q));
        if (old2 == SENT) return;            // first matrix arriver
        float tot = q + __uint_as_float(old2);
        st_relaxed_u32(cs, SENT);
        float hv = tanhf(tot);
        st_relaxed_f32(&g_h[l][t & 1][r], hv);
        if (l == 3) st_relaxed_f32(&g_h3[(size_t)t * HID + r], hv);
    }
}

// ---------------- generic single half-unit (fallback / extras) -------------
__device__ __forceinline__ void process_hu(int m, int half, int r, int w, int lane,
                                           const float (*sm_h)[HID],
                                           const float* __restrict__ Bh)
{
    const int l = (m < 4) ? m : m - 3;
    const int t = w - l;
    if ((unsigned)t >= (unsigned)SEQ) return;
    const int hsrc = (m < 4) ? m : m - 4;
    const uint4* w4 = (const uint4*)(g_w16 + ((size_t)m * HID + r) * HID) + half * 128;
    const float4* h4 = (const float4*)(sm_h[hsrc]) + half * 256;
    float a0 = 0.f, a1 = 0.f, a2 = 0.f, a3 = 0.f;
    #pragma unroll
    for (int i = 0; i < 4; ++i) {
        const int idx = lane + 32 * i;
        uint4 wv = (m < 3) ? w4[idx] : __ldcg(w4 + idx);
        float4 h0 = h4[2 * idx];
        float4 h1 = h4[2 * idx + 1];
        float2 c;
        c = __half22float2(*(__half2*)&wv.x); a0 = fmaf(c.x, h0.x, a0); a1 = fmaf(c.y, h0.y, a1);
        c = __half22float2(*(__half2*)&wv.y); a2 = fmaf(c.x, h0.z, a2); a3 = fmaf(c.y, h0.w, a3);
        c = __half22float2(*(__half2*)&wv.z); a0 = fmaf(c.x, h1.x, a0); a1 = fmaf(c.y, h1.y, a1);
        c = __half22float2(*(__half2*)&wv.w); a2 = fmaf(c.x, h1.z, a2); a3 = fmaf(c.y, h1.w, a3);
    }
    float acc = (a0 + a1) + (a2 + a3);
    #pragma unroll
    for (int s = 16; s; s >>= 1) acc += __shfl_xor_sync(0xffffffffu, acc, s);
    if (lane == 0) finish_row_partial(m, r, t, l, acc, Bh);   // FIXED arg order
}

// ---------------- wavefront RNN kernel ----------------
__global__ __launch_bounds__(1024, 1) void rnn_wave_kernel(
    const float* __restrict__ Bh,
    float*                    hfinal_out)
{
    __shared__ float sm_h[NL][HID];   // 32KB

    const unsigned nb  = gridDim.x;
    const int tid      = threadIdx.x;
    const int gtid     = blockIdx.x * 1024 + tid;
    const int nthreads = (int)nb * 1024;

    for (int i = gtid; i < NL * 2 * HID; i += nthreads) ((float*)g_h)[i] = 0.f;
    for (int i = gtid; i < NMAT * HID; i += nthreads)   g_hslot[i] = SENT;
    for (int i = gtid; i < 3 * HID; i += nthreads)      g_slot[i]  = SENT;
    for (int i = gtid; i < NCTR * 64; i += nthreads)    g_ctr[i]   = 0u;
    init_barrier(nb);

    const int lane  = tid & 31;
    const int gw    = (blockIdx.x << 5) + (tid >> 5);
    const int nwarp = (int)nb * 32;

    // ---- wave-invariant work assignment (hoisted out of the wave loop) ----
    const int flat0 = 6 * gw;                       // first half-unit index
    const bool in_range = flat0 < HU_TOTAL;
    const bool full6    = flat0 + 5 < HU_TOTAL;
    const int  seg      = flat0 >> 11;              // (matrix, half) segment
    const int  r0       = flat0 & (HID - 1);
    const bool fast     = full6 && (r0 <= HID - 6); // 6 rows, one segment
    const int  m        = seg >> 1;
    const int  half     = seg & 1;
    const int  l        = (m < 4) ? m : m - 3;
    const int  hsrc     = (m < 4) ? m : m - 4;
    // extras (when HU_TOTAL > 6*nwarp): spread one per (nwarp/E)-th warp
    const int E = HU_TOTAL - 6 * nwarp;
    int extra_flat = -1;
    if (E > 0) {
        const int stride = nwarp / E;
        if (gw % stride == 0 && gw / stride < E)
            extra_flat = 6 * nwarp + gw / stride;
    }

    const uint4* wr[6];
    #pragma unroll
    for (int j = 0; j < 6; ++j)
        wr[j] = (const uint4*)(g_w16 + (size_t)m * HID * HID) + (size_t)(r0 + j) * 256 + half * 128;
    const float4* h4 = (const float4*)(sm_h[hsrc]) + half * 256;

    unsigned epoch = 0;

    for (int w = 0; w < SEQ + NL - 1; ++w) {
        // stage the 4 h-buffers this wave reads (parity-resolved)
        for (int i = tid; i < NL * (HID / 4); i += 1024) {
            const int sl = i >> 9;
            const int j  = i & 511;
            ((float4*)sm_h[sl])[j] =
                __ldcg((const float4*)g_h[sl][(w + sl + 1) & 1] + j);
        }
        __syncthreads();

        if (fast) {
            const int t = w - l;
            if ((unsigned)t < (unsigned)SEQ) {
                float a[6][2];
                #pragma unroll
                for (int j = 0; j < 6; ++j) { a[j][0] = 0.f; a[j][1] = 0.f; }
                #pragma unroll
                for (int i = 0; i < 4; ++i) {
                    const int idx = lane + 32 * i;
                    const float4 h0 = h4[2 * idx];
                    const float4 h1 = h4[2 * idx + 1];
                    uint4 wv[6];
                    if (m < 3) {
                        #pragma unroll
                        for (int j = 0; j < 6; ++j) wv[j] = wr[j][idx];
                    } else {
                        #pragma unroll
                        for (int j = 0; j < 6; ++j) wv[j] = __ldcg(wr[j] + idx);
                    }
                    #pragma unroll
                    for (int j = 0; j < 6; ++j) {
                        float2 c;
                        c = __half22float2(*(__half2*)&wv[j].x);
                        a[j][0] = fmaf(c.x, h0.x, a[j][0]); a[j][1] = fmaf(c.y, h0.y, a[j][1]);
                        c = __half22float2(*(__half2*)&wv[j].y);
                        a[j][0] = fmaf(c.x, h0.z, a[j][0]); a[j][1] = fmaf(c.y, h0.w, a[j][1]);
                        c = __half22float2(*(__half2*)&wv[j].z);
                        a[j][0] = fmaf(c.x, h1.x, a[j][0]); a[j][1] = fmaf(c.y, h1.y, a[j][1]);
                        c = __half22float2(*(__half2*)&wv[j].w);
                        a[j][0] = fmaf(c.x, h1.z, a[j][0]); a[j][1] = fmaf(c.y, h1.w, a[j][1]);
                    }
                }
                #pragma unroll
                for (int j = 0; j < 6; ++j) {
                    float acc = a[j][0] + a[j][1];
                    #pragma unroll
                    for (int s = 16; s; s >>= 1)
                        acc += __shfl_xor_sync(0xffffffffu, acc, s);
                    if (lane == 0)
                        finish_row_partial(m, r0 + j, t, l, acc, Bh);
                }
            }
        } else if (in_range) {
            #pragma unroll
            for (int j = 0; j < 6; ++j) {
                const int flat = flat0 + j;
                if (flat < HU_TOTAL) {
                    const int sg = flat >> 11;
                    process_hu(sg >> 1, sg & 1, flat & (HID - 1), w, lane, sm_h, Bh);
                }
            }
        }
        if (extra_flat >= 0) {
            const int sg = extra_flat >> 11;
            process_hu(sg >> 1, sg & 1, extra_flat & (HID - 1), w, lane, sm_h, Bh);
        }

        ++epoch;
        wave_barrier(nb, epoch);
    }

    if (hfinal_out) {
        for (int i = gtid; i < NL * HID; i += nthreads)
            hfinal_out[i] = __ldcg(&g_h[i >> 11][1][i & (HID - 1)]);
    }
}

// ---------------- generic C[M,N] = A[M,K] * B[N,K]^T (+bias) ----------------
__global__ __launch_bounds__(256) void gemm_abt_kernel(
    const float* __restrict__ A,
    const float* __restrict__ B,
    float*       __restrict__ C,
    const float* __restrict__ bias,
    int M, int N, int K)
{
    __shared__ float As[16][68];
    __shared__ float Bs[16][68];

    const int tn  = blockIdx.x * 64;
    const int tm  = blockIdx.y * 64;
    const int tid = threadIdx.x;
    const int tx  = tid & 15;
    const int ty  = tid >> 4;
    const int lr  = tid >> 2;
    const int lq  = tid & 3;

    float acc[4][4];
    #pragma unroll
    for (int i = 0; i < 4; ++i)
        #pragma unroll
        for (int j = 0; j < 4; ++j) acc[i][j] = 0.f;

    for (int k0 = 0; k0 < K; k0 += 16) {
        float4 a4 = *(const float4*)(A + (size_t)(tm + lr) * K + k0 + lq * 4);
        float4 b4 = *(const float4*)(B + (size_t)(tn + lr) * K + k0 + lq * 4);
        As[lq * 4 + 0][lr] = a4.x; As[lq * 4 + 1][lr] = a4.y;
        As[lq * 4 + 2][lr] = a4.z; As[lq * 4 + 3][lr] = a4.w;
        Bs[lq * 4 + 0][lr] = b4.x; Bs[lq * 4 + 1][lr] = b4.y;
        Bs[lq * 4 + 2][lr] = b4.z; Bs[lq * 4 + 3][lr] = b4.w;
        __syncthreads();
        #pragma unroll
        for (int kk = 0; kk < 16; ++kk) {
            float a0 = As[kk][ty * 4 + 0], a1 = As[kk][ty * 4 + 1];
            float a2 = As[kk][ty * 4 + 2], a3 = As[kk][ty * 4 + 3];
            float b0 = Bs[kk][tx * 4 + 0], b1 = Bs[kk][tx * 4 + 1];
            float b2 = Bs[kk][tx * 4 + 2], b3 = Bs[kk][tx * 4 + 3];
            acc[0][0] = fmaf(a0, b0, acc[0][0]); acc[0][1] = fmaf(a0, b1, acc[0][1]);
            acc[0][2] = fmaf(a0, b2, acc[0][2]); acc[0][3] = fmaf(a0, b3, acc[0][3]);
            acc[1][0] = fmaf(a1, b0, acc[1][0]); acc[1][1] = fmaf(a1, b1, acc[1][1]);
            acc[1][2] = fmaf(a1, b2, acc[1][2]); acc[1][3] = fmaf(a1, b3, acc[1][3]);
            acc[2][0] = fmaf(a2, b0, acc[2][0]); acc[2][1] = fmaf(a2, b1, acc[2][1]);
            acc[2][2] = fmaf(a2, b2, acc[2][2]); acc[2][3] = fmaf(a2, b3, acc[2][3]);
            acc[3][0] = fmaf(a3, b0, acc[3][0]); acc[3][1] = fmaf(a3, b1, acc[3][1]);
            acc[3][2] = fmaf(a3, b2, acc[3][2]); acc[3][3] = fmaf(a3, b3, acc[3][3]);
        }
        __syncthreads();
    }

    #pragma unroll
    for (int i = 0; i < 4; ++i) {
        const int row = tm + ty * 4 + i;
        #pragma unroll
        for (int j = 0; j < 4; ++j) {
            const int col = tn + tx * 4 + j;
            float v = acc[i][j];
            if (bias) v += bias[col];
            C[(size_t)row * N + col] = v;
        }
    }
}

// ---------------- launch ----------------
extern "C" void kernel_launch(void* const* d_in, const int* in_sizes, int n_in,
                              void* d_out, int out_size)
{
    const float* x   = (const float*)d_in[0];
    const float* Wh  = (const float*)d_in[1];
    const float* Whh = (const float*)d_in[2];
    const float* Wx  = (const float*)d_in[3];
    const float* Wy  = (const float*)d_in[4];
    const float* Bh  = (const float*)d_in[5];
    const float* By  = (const float*)d_in[6];
    float* out = (float*)d_out;

    (void)in_sizes; (void)n_in;

    void* p_xin = nullptr;
    void* p_h3  = nullptr;
    cudaGetSymbolAddress(&p_xin, g_xin);
    cudaGetSymbolAddress(&p_h3,  g_h3);

    int nsm = 0;
    cudaDeviceGetAttribute(&nsm, cudaDevAttrMultiProcessorCount, 0);
    if (nsm <= 0) nsm = 148;

    cudaFuncSetAttribute(rnn_wave_kernel,
                         cudaFuncAttributePreferredSharedMemoryCarveout, 15);

    // 1) fp32 -> fp16 weight conversion
    convert_w_kernel<<<nsm * 8, 256>>>(Wh, Whh);

    // 2) xin = x @ Wx^T
    {
        dim3 grid(HID / 64, SEQ / 64);
        gemm_abt_kernel<<<grid, 256>>>(x, Wx, (float*)p_xin, nullptr,
                                       SEQ, HID, INSZ);
    }

    // 3) pad so the wave kernel is the 4th execution (ncu capture slot)
    noop_kernel<<<1, 32>>>();

    // 4) wavefront recurrence (persistent kernel, grid = #SMs)
    {
        float* hfinal = nullptr;
        if (out_size >= SEQ * INSZ + NL * HID)
            hfinal = out + (size_t)SEQ * INSZ;
        rnn_wave_kernel<<<nsm, 1024>>>(Bh, hfinal);
    }

    // 5) ys = h3_all @ Wy^T + By
    {
        dim3 grid(INSZ / 64, SEQ / 64);
        gemm_abt_kernel<<<grid, 256>>>((const float*)p_h3, Wy, out, By,
                                       SEQ, INSZ, HID);
    }
}